// round 1
// baseline (speedup 1.0000x reference)
#include <cuda_runtime.h>
#include <cstdint>

// ---------------------------------------------------------------------------
// TT-Embedding on GB300:
//   IN_MODES  = (40, 32, 25)  -> V = 32000
//   OUT_MODES = (8, 8, 16)    -> E = 1024
//   RANKS     = (1, 16, 16, 1)
//   out[t, e] with e = x*128 + y*16 + z,  v -> (p,q,r)
//   out[x,y,z] = sum_{b,c} core0[0,x,p,b] * core1[b,y,q,c] * core2[c,z,r,0]
//
// Strategy: precompute PQ[p,q][xy][c] = sum_b core0[x,p,b]*core1[b,y,q,c]
// (1280 * 1024 floats = 5.24 MB, L2-resident), then each token is a tiny
// 64x16 @ 16x16 contraction with coalesced 1024-float output.
// ---------------------------------------------------------------------------

#define NP 40
#define NQ 32
#define NR 25
#define R  16           // bond rank
#define E_DIM 1024

// Scratch (device-global: no allocations allowed)
__device__ float g_PQ[NP * NQ * 64 * 16];   // [(p*32+q)*1024 + xy*16 + c]
__device__ int   g_is64;

// ---------------------------------------------------------------------------
// Kernel 0: detect whether input_ids are int64 (high words all zero) or int32.
// Single block -> deterministic, graph-capturable.
// ---------------------------------------------------------------------------
__global__ void tt_detect_kernel(const unsigned int* __restrict__ w, int n_tok) {
    __shared__ int s_ok;
    if (threadIdx.x == 0) s_ok = 1;
    __syncthreads();
    int ok = 1;
    for (int i = threadIdx.x; i < n_tok; i += blockDim.x) {
        if (w[2 * i + 1] != 0u) ok = 0;
    }
    if (!ok) atomicAnd(&s_ok, 0);
    __syncthreads();
    if (threadIdx.x == 0) g_is64 = s_ok;
}

// ---------------------------------------------------------------------------
// Kernel 1: build PQ table. One block per (p,q). 256 threads.
//   core0: (1, 8, 40, 16)   c0[(x*40 + p)*16 + b]
//   core1: (16, 8, 32, 16)  c1[((b*8 + y)*32 + q)*16 + c] = c1[by*512 + q*16 + c]
// ---------------------------------------------------------------------------
__global__ __launch_bounds__(256) void tt_build_pq_kernel(
    const float* __restrict__ c0, const float* __restrict__ c1)
{
    const int pq = blockIdx.x;
    const int p = pq / NQ;
    const int q = pq % NQ;
    const int tid = threadIdx.x;

    __shared__ float sA[8 * 16];     // A[x][b]
    __shared__ float sM1[128 * 16];  // M1[(b*8+y)][c]

    if (tid < 128) {
        int x = tid >> 4, b = tid & 15;
        sA[tid] = c0[(x * NP + p) * 16 + b];
    }
    #pragma unroll
    for (int i = tid; i < 2048; i += 256) {
        int by = i >> 4, c = i & 15;
        sM1[i] = c1[by * 512 + q * 16 + c];
    }
    __syncthreads();

    #pragma unroll
    for (int k = 0; k < 4; k++) {
        int o  = tid + 256 * k;      // o = xy*16 + c
        int xy = o >> 4;
        int c  = o & 15;
        int x  = xy >> 3;
        int y  = xy & 7;
        float s = 0.f;
        #pragma unroll
        for (int b = 0; b < 16; b++)
            s = fmaf(sA[x * 16 + b], sM1[(b * 8 + y) * 16 + c], s);
        g_PQ[pq * 1024 + o] = s;
    }
}

// ---------------------------------------------------------------------------
// Kernel 2: gather. One block per token, 256 threads.
//   core2: (16, 16, 25, 1)  c2[(c*16 + z)*25 + r]
//   out[t*1024 + e],  e = tid + 256k (coalesced),  z = tid&15 fixed per thread
// ---------------------------------------------------------------------------
__global__ __launch_bounds__(256) void tt_gather_kernel(
    const float* __restrict__ c2, const void* __restrict__ ids,
    float* __restrict__ out)
{
    const int t   = blockIdx.x;
    const int tid = threadIdx.x;

    long long v;
    if (g_is64) v = ((const long long*)ids)[t];
    else        v = (long long)((const int*)ids)[t];

    const int p = (int)(v / 800);
    const int q = (int)((v / 25) % 32);
    const int r = (int)(v % 25);

    __shared__ float sPQ[1024];          // [xy*16 + c]
    __shared__ float sM2T[16 * 17];      // [z*17 + c], padded (conflict-free)

    {
        const float* src = &g_PQ[(p * NQ + q) * 1024];
        #pragma unroll
        for (int k = 0; k < 4; k++)
            sPQ[tid + 256 * k] = src[tid + 256 * k];
    }
    if (tid < 256) {
        int z = tid >> 4, c = tid & 15;
        sM2T[z * 17 + c] = c2[(c * 16 + z) * NR + r];
    }
    __syncthreads();

    const int z = tid & 15;

    // M2 row for this thread's z: 16 registers, conflict-free loads
    float m2[16];
    #pragma unroll
    for (int c = 0; c < 16; c++) m2[c] = sM2T[z * 17 + c];

    float* dst = out + (size_t)t * E_DIM;

    #pragma unroll
    for (int k = 0; k < 4; k++) {
        const int xy = (tid >> 4) + 16 * k;
        // sPQ row reads are warp-broadcast (16 lanes share each xy)
        const float4* row = (const float4*)&sPQ[xy * 16];
        float4 a0 = row[0], a1 = row[1], a2 = row[2], a3 = row[3];
        float s = 0.f;
        s = fmaf(a0.x, m2[0],  s); s = fmaf(a0.y, m2[1],  s);
        s = fmaf(a0.z, m2[2],  s); s = fmaf(a0.w, m2[3],  s);
        s = fmaf(a1.x, m2[4],  s); s = fmaf(a1.y, m2[5],  s);
        s = fmaf(a1.z, m2[6],  s); s = fmaf(a1.w, m2[7],  s);
        s = fmaf(a2.x, m2[8],  s); s = fmaf(a2.y, m2[9],  s);
        s = fmaf(a2.z, m2[10], s); s = fmaf(a2.w, m2[11], s);
        s = fmaf(a3.x, m2[12], s); s = fmaf(a3.y, m2[13], s);
        s = fmaf(a3.z, m2[14], s); s = fmaf(a3.w, m2[15], s);
        dst[tid + 256 * k] = s;
    }
}

// ---------------------------------------------------------------------------
extern "C" void kernel_launch(void* const* d_in, const int* in_sizes, int n_in,
                              void* d_out, int out_size) {
    const float* c0  = (const float*)d_in[0];
    const float* c1  = (const float*)d_in[1];
    const float* c2  = (const float*)d_in[2];
    const void*  ids = d_in[3];
    float* out = (float*)d_out;

    const int n_tok = in_sizes[3];   // 16384 elements regardless of dtype

    tt_detect_kernel<<<1, 1024>>>((const unsigned int*)ids, n_tok);
    tt_build_pq_kernel<<<NP * NQ, 256>>>(c0, c1);
    tt_gather_kernel<<<n_tok, 256>>>(c2, ids, out);
}

// round 2
// speedup vs baseline: 1.0940x; 1.0940x over previous
#include <cuda_runtime.h>
#include <cstdint>

// ---------------------------------------------------------------------------
// TT-Embedding on GB300 (sm_103a):
//   IN_MODES  = (40, 32, 25)  -> V = 32000
//   OUT_MODES = (8, 8, 16)    -> E = 1024
//   RANKS     = (1, 16, 16, 1)
//   out[t, e], e = x*128 + y*16 + z;  v -> (p = v/800, q = (v/25)%32, r = v%25)
//   out[x,y,z] = sum_{b,c} core0[0,x,p,b] * core1[b,y,q,c] * core2[c,z,r,0]
//
// PQ[p,q][xy][c] = sum_b core0*core1  (5.24 MB, L2-resident), stored in
// PAIR LAYOUT: float2 { PQ[xy,c], PQ[xy|16,c] } so the gather's packed
// fma.rn.f32x2 operand comes straight from LDS.128 with zero packing cost.
// ---------------------------------------------------------------------------

#define NP 40
#define NQ 32
#define NR 25
#define E_DIM 1024

__device__ float g_PQ[NP * NQ * 1024];   // pair layout, see below
__device__ int   g_is64;

// ---------------------------------------------------------------------------
// Kernel 0: reset detection flag (graph replays re-run this).
// ---------------------------------------------------------------------------
__global__ void tt_init_kernel() { g_is64 = 1; }

// ---------------------------------------------------------------------------
// Kernel 1: build PQ table (pair layout) + int64 detection folded in.
//   core0: (1, 8, 40, 16)   c0[(x*40 + p)*16 + b]
//   core1: (16, 8, 32, 16)  c1[by*512 + q*16 + c]
// Pair layout: po = ((g*16 + c) << 1) | sel,
//   g = ((xy>>5)<<4) | (xy&15),  sel = (xy>>4)&1   (pairs are (xy, xy|16))
// We iterate po = tid + 256k directly so global stores stay coalesced.
// ---------------------------------------------------------------------------
__global__ __launch_bounds__(256) void tt_build_pq_kernel(
    const float* __restrict__ c0, const float* __restrict__ c1,
    const unsigned int* __restrict__ idw, int n_tok)
{
    const int pq = blockIdx.x;
    const int p = pq / NQ;
    const int q = pq % NQ;
    const int tid = threadIdx.x;

    // --- folded int64 detection: first 64 blocks, 1 high-word each/thread ---
    if (blockIdx.x < 64) {
        int j = blockIdx.x * 256 + tid;            // 64*256 = 16384 = n_tok
        int bad = (j < n_tok) && (idw[2 * j + 1] != 0u);
        unsigned m = __ballot_sync(0xffffffffu, bad);
        if ((tid & 31) == 0 && m) atomicAnd(&g_is64, 0);
    }

    __shared__ float sA[8 * 16];     // A[x][b]
    __shared__ float sM1[128 * 16];  // M1[(b*8+y)][c]

    if (tid < 128) {
        int x = tid >> 4, b = tid & 15;
        sA[tid] = c0[(x * NP + p) * 16 + b];
    }
    #pragma unroll
    for (int i = tid; i < 2048; i += 256) {
        int by = i >> 4, c = i & 15;
        sM1[i] = c1[by * 512 + q * 16 + c];
    }
    __syncthreads();

    #pragma unroll
    for (int k = 0; k < 4; k++) {
        int po  = tid + 256 * k;                 // pair-layout offset
        int sel = po & 1;
        int idx = po >> 1;
        int c   = idx & 15;
        int g   = idx >> 4;
        int xy  = ((g >> 4) << 5) | (sel << 4) | (g & 15);
        int x   = xy >> 3;
        int y   = xy & 7;
        float s = 0.f;
        #pragma unroll
        for (int b = 0; b < 16; b++)
            s = fmaf(sA[x * 16 + b], sM1[(b * 8 + y) * 16 + c], s);
        g_PQ[pq * 1024 + po] = s;
    }
}

// ---------------------------------------------------------------------------
// Kernel 2: gather. One block per token, 256 threads.
//   core2: (16, 16, 25, 1)  c2[(c*16 + z)*25 + r]
// Thread tid -> z = tid&15 fixed; produces out[tid + 256k], k=0..3 as two
// packed f32x2 chains: pair (xy, xy+16) shares the multiplier m2[c,z].
// ---------------------------------------------------------------------------
__global__ __launch_bounds__(256) void tt_gather_kernel(
    const float* __restrict__ c2, const void* __restrict__ ids,
    float* __restrict__ out)
{
    const int t   = blockIdx.x;
    const int tid = threadIdx.x;

    long long v;
    if (g_is64) v = ((const long long*)ids)[t];
    else        v = (long long)((const int*)ids)[t];

    const int p = (int)(v / 800);
    const int q = (int)((v / 25) % 32);
    const int r = (int)(v % 25);

    __shared__ float4 sPQ4[256];      // raw copy of pair-layout slice (4 KB)
    __shared__ float  sM2T[16 * 17];  // [z*17 + c], padded

    sPQ4[tid] = ((const float4*)(g_PQ + (p * NQ + q) * 1024))[tid];
    {
        int z = tid >> 4, c = tid & 15;
        sM2T[z * 17 + c] = c2[(c * 16 + z) * NR + r];
    }
    __syncthreads();

    const int z = tid & 15;

    // Broadcast-pack m2: m2p[c] = {m2[c], m2[c]}  (16 movs, once per thread)
    unsigned long long m2p[16];
    #pragma unroll
    for (int c = 0; c < 16; c++) {
        float m = sM2T[z * 17 + c];
        asm("mov.b64 %0, {%1, %2};" : "=l"(m2p[c]) : "f"(m), "f"(m));
    }

    const float2* sP2 = (const float2*)sPQ4;
    float* dst = out + (size_t)t * E_DIM;

    #pragma unroll
    for (int h = 0; h < 2; h++) {
        const int g = (tid >> 4) + 16 * h;
        const float4* rp = (const float4*)(sP2 + g * 16);  // 8 x float4
        unsigned long long acc = 0ull;                      // {0.f, 0.f}
        #pragma unroll
        for (int cc = 0; cc < 8; cc++) {
            float4 pr = rp[cc];   // float2 pairs for c = 2cc, 2cc+1
            unsigned long long b0, b1;
            asm("mov.b64 %0, {%1, %2};" : "=l"(b0) : "f"(pr.x), "f"(pr.y));
            asm("mov.b64 %0, {%1, %2};" : "=l"(b1) : "f"(pr.z), "f"(pr.w));
            asm("fma.rn.f32x2 %0, %1, %2, %0;" : "+l"(acc) : "l"(b0), "l"(m2p[2 * cc]));
            asm("fma.rn.f32x2 %0, %1, %2, %0;" : "+l"(acc) : "l"(b1), "l"(m2p[2 * cc + 1]));
        }
        float lo, hi;
        asm("mov.b64 {%0, %1}, %2;" : "=f"(lo), "=f"(hi) : "l"(acc));
        dst[tid + 512 * h]       = lo;   // e = xy*16 + z
        dst[tid + 256 + 512 * h] = hi;   // e = (xy+16)*16 + z
    }
}

// ---------------------------------------------------------------------------
extern "C" void kernel_launch(void* const* d_in, const int* in_sizes, int n_in,
                              void* d_out, int out_size) {
    const float* c0  = (const float*)d_in[0];
    const float* c1  = (const float*)d_in[1];
    const float* c2  = (const float*)d_in[2];
    const void*  ids = d_in[3];
    float* out = (float*)d_out;

    const int n_tok = in_sizes[3];   // 16384 elements regardless of dtype

    tt_init_kernel<<<1, 1>>>();
    tt_build_pq_kernel<<<NP * NQ, 256>>>(c0, c1, (const unsigned int*)ids, n_tok);
    tt_gather_kernel<<<n_tok, 256>>>(c2, ids, out);
}